// round 1
// baseline (speedup 1.0000x reference)
#include <cuda_runtime.h>
#include <cstdint>

// One CTA per batch row. Row (F floats = 64KB) is staged in dynamic smem,
// gathers hit smem, per-thread values live in registers across the mean
// reduction, epilogue writes coalesced float4.

#define THREADS 512
#define MAXCHUNK 8   // float4 chunks per thread: N/4/THREADS = 16384/4/512 = 8

__global__ __launch_bounds__(THREADS, 2)
void sensory_kernel(const float* __restrict__ enc,
                    const float* __restrict__ w,
                    const int*   __restrict__ pref,
                    float* __restrict__ out,
                    int N, int F, int fmask /* F-1 if pow2 else 0 */)
{
    extern __shared__ float srow[];
    __shared__ float warpsums[THREADS / 32];
    __shared__ float s_mean;

    const int b = blockIdx.x;
    const float* row = enc + (size_t)b * (size_t)F;

    // ---- stage row into smem (streaming, coalesced float4) ----
    {
        const float4* row4 = (const float4*)row;
        float4* s4 = (float4*)srow;
        const int nf4 = F >> 2;
        for (int i = threadIdx.x; i < nf4; i += THREADS) {
            s4[i] = __ldcs(row4 + i);
        }
    }
    __syncthreads();

    // ---- gather into registers + local sum ----
    const int n4count = N >> 2;                 // float4 elements over N
    const int4*   pref4 = (const int4*)pref;
    const float4* w4    = (const float4*)w;

    float4 vals[MAXCHUNK];
    float lsum = 0.0f;
    int nchunk = 0;

    #pragma unroll
    for (int k = 0; k < MAXCHUNK; ++k) {
        int i4 = threadIdx.x + k * THREADS;
        if (i4 < n4count) {
            int4   p  = pref4[i4];
            float4 ww = w4[i4];
            float4 v;
            if (fmask) {
                v.x = srow[p.x & fmask] * ww.x;
                v.y = srow[p.y & fmask] * ww.y;
                v.z = srow[p.z & fmask] * ww.z;
                v.w = srow[p.w & fmask] * ww.w;
            } else {
                v.x = srow[(unsigned)p.x % (unsigned)F] * ww.x;
                v.y = srow[(unsigned)p.y % (unsigned)F] * ww.y;
                v.z = srow[(unsigned)p.z % (unsigned)F] * ww.z;
                v.w = srow[(unsigned)p.w % (unsigned)F] * ww.w;
            }
            vals[k] = v;
            lsum += (v.x + v.y) + (v.z + v.w);
            nchunk = k + 1;
        }
    }

    // ---- block reduction for mean ----
    #pragma unroll
    for (int off = 16; off > 0; off >>= 1)
        lsum += __shfl_down_sync(0xFFFFFFFFu, lsum, off);

    const int lane = threadIdx.x & 31;
    const int wid  = threadIdx.x >> 5;
    if (lane == 0) warpsums[wid] = lsum;
    __syncthreads();

    if (wid == 0) {
        float s = (lane < (THREADS / 32)) ? warpsums[lane] : 0.0f;
        #pragma unroll
        for (int off = 8; off > 0; off >>= 1)
            s += __shfl_down_sync(0xFFFFFFFFu, s, off);
        if (lane == 0) s_mean = s / (float)N;
    }
    __syncthreads();

    const float sub = 0.1f * s_mean;

    // ---- epilogue: subtract + relu, coalesced streaming float4 stores ----
    float4* out4 = (float4*)(out + (size_t)b * (size_t)N);
    #pragma unroll
    for (int k = 0; k < MAXCHUNK; ++k) {
        if (k < nchunk) {
            int i4 = threadIdx.x + k * THREADS;
            float4 v = vals[k];
            float4 o;
            o.x = fmaxf(v.x - sub, 0.0f);
            o.y = fmaxf(v.y - sub, 0.0f);
            o.z = fmaxf(v.z - sub, 0.0f);
            o.w = fmaxf(v.w - sub, 0.0f);
            __stcs(out4 + i4, o);
        }
    }
}

extern "C" void kernel_launch(void* const* d_in, const int* in_sizes, int n_in,
                              void* d_out, int out_size)
{
    const float* enc  = (const float*)d_in[0];
    const float* w    = (const float*)d_in[1];
    const int*   pref = (const int*)d_in[2];
    float*       out  = (float*)d_out;

    const int N = in_sizes[1];
    const int B = out_size / N;
    const int F = (int)((long long)in_sizes[0] / (long long)B);
    const int fmask = ((F & (F - 1)) == 0) ? (F - 1) : 0;

    const int smem = F * (int)sizeof(float);
    cudaFuncSetAttribute(sensory_kernel,
                         cudaFuncAttributeMaxDynamicSharedMemorySize, smem);

    sensory_kernel<<<B, THREADS, smem>>>(enc, w, pref, out, N, F, fmask);
}

// round 2
// speedup vs baseline: 1.2364x; 1.2364x over previous
#include <cuda_runtime.h>
#include <cstdint>

// Persistent double-buffered kernel: grid = #SMs, each CTA loops over rows.
// Row i+1 streams into the spare smem buffer via cp.async.bulk (TMA) while
// row i is gathered/reduced/stored. pref/weights live in registers for the
// whole kernel (row-invariant).

#define THREADS 512
#define MAXCHUNK 8   // N/4/THREADS = 16384/4/512

__global__ __launch_bounds__(THREADS, 1)
void sensory_persistent(const float* __restrict__ enc,
                        const float* __restrict__ w,
                        const int*   __restrict__ pref,
                        float* __restrict__ out,
                        int B, int N, int F, int fmask)
{
    extern __shared__ __align__(128) unsigned char smem_dyn[];
    float* buf0 = (float*)smem_dyn;
    float* buf1 = (float*)(smem_dyn + (size_t)F * 4u);
    __shared__ __align__(8) unsigned long long mbar[2];
    __shared__ float warpsums[THREADS / 32];
    __shared__ float s_mean;

    const int tid = threadIdx.x;
    const unsigned rowbytes = (unsigned)F * 4u;

    const uint32_t b_bar0 = (uint32_t)__cvta_generic_to_shared(&mbar[0]);
    const uint32_t b_bar1 = (uint32_t)__cvta_generic_to_shared(&mbar[1]);
    const uint32_t b_buf0 = (uint32_t)__cvta_generic_to_shared(buf0);
    const uint32_t b_buf1 = (uint32_t)__cvta_generic_to_shared(buf1);

    if (tid == 0) {
        asm volatile("mbarrier.init.shared::cta.b64 [%0], 1;" :: "r"(b_bar0) : "memory");
        asm volatile("mbarrier.init.shared::cta.b64 [%0], 1;" :: "r"(b_bar1) : "memory");
        asm volatile("fence.proxy.async.shared::cta;" ::: "memory");
    }
    __syncthreads();

    // ---- preload prefs (as byte offsets) and weights into registers ----
    const int n4 = N >> 2;
    int4   poff[MAXCHUNK];
    float4 wv[MAXCHUNK];
    {
        const int4*   pref4 = (const int4*)pref;
        const float4* w4    = (const float4*)w;
        #pragma unroll
        for (int k = 0; k < MAXCHUNK; ++k) {
            int i4 = tid + k * THREADS;
            if (i4 < n4) {
                int4 p = pref4[i4];
                if (fmask) {
                    p.x = (p.x & fmask) << 2;
                    p.y = (p.y & fmask) << 2;
                    p.z = (p.z & fmask) << 2;
                    p.w = (p.w & fmask) << 2;
                } else {
                    p.x = (int)((unsigned)p.x % (unsigned)F) << 2;
                    p.y = (int)((unsigned)p.y % (unsigned)F) << 2;
                    p.z = (int)((unsigned)p.z % (unsigned)F) << 2;
                    p.w = (int)((unsigned)p.w % (unsigned)F) << 2;
                }
                poff[k] = p;
                wv[k]   = w4[i4];
            }
        }
    }

    const int G = gridDim.x;
    int ph0 = 0, ph1 = 0;
    int cur = 0;

    int r = blockIdx.x;
    // prologue: kick off TMA for first row into buf0
    if (r < B && tid == 0) {
        asm volatile("mbarrier.arrive.expect_tx.shared::cta.b64 _, [%0], %1;"
                     :: "r"(b_bar0), "r"(rowbytes) : "memory");
        asm volatile("cp.async.bulk.shared::cta.global.mbarrier::complete_tx::bytes "
                     "[%0], [%1], %2, [%3];"
                     :: "r"(b_buf0), "l"(enc + (size_t)r * (size_t)F),
                        "r"(rowbytes), "r"(b_bar0) : "memory");
    }

    for (; r < B; r += G) {
        const int rn = r + G;
        // issue next row into the other buffer (free since last iteration's barrier)
        if (rn < B && tid == 0) {
            const uint32_t nbar = cur ? b_bar0 : b_bar1;
            const uint32_t nbuf = cur ? b_buf0 : b_buf1;
            asm volatile("mbarrier.arrive.expect_tx.shared::cta.b64 _, [%0], %1;"
                         :: "r"(nbar), "r"(rowbytes) : "memory");
            asm volatile("cp.async.bulk.shared::cta.global.mbarrier::complete_tx::bytes "
                         "[%0], [%1], %2, [%3];"
                         :: "r"(nbuf), "l"(enc + (size_t)rn * (size_t)F),
                            "r"(rowbytes), "r"(nbar) : "memory");
        }

        // ---- wait for current buffer (acquire orders TMA writes) ----
        {
            const uint32_t mb  = cur ? b_bar1 : b_bar0;
            const uint32_t par = (uint32_t)(cur ? ph1 : ph0);
            uint32_t done;
            asm volatile("{ .reg .pred p; "
                         "mbarrier.try_wait.parity.acquire.cta.shared::cta.b64 p, [%1], %2; "
                         "selp.b32 %0, 1, 0, p; }"
                         : "=r"(done) : "r"(mb), "r"(par) : "memory");
            if (!done) {
                asm volatile("{ .reg .pred P1; "
                             "WL%=: mbarrier.try_wait.parity.acquire.cta.shared::cta.b64 P1, [%0], %1, 0x989680; "
                             "@P1 bra.uni WD%=; bra.uni WL%=; WD%=: }"
                             :: "r"(mb), "r"(par) : "memory");
            }
            if (cur) ph1 ^= 1; else ph0 ^= 1;
        }

        const char* srow = (const char*)(cur ? buf1 : buf0);

        // ---- gather into registers + local sum ----
        float lsum = 0.0f;
        float4 vals[MAXCHUNK];
        #pragma unroll
        for (int k = 0; k < MAXCHUNK; ++k) {
            int i4 = tid + k * THREADS;
            if (i4 < n4) {
                float4 v;
                v.x = *(const float*)(srow + poff[k].x) * wv[k].x;
                v.y = *(const float*)(srow + poff[k].y) * wv[k].y;
                v.z = *(const float*)(srow + poff[k].z) * wv[k].z;
                v.w = *(const float*)(srow + poff[k].w) * wv[k].w;
                vals[k] = v;
                lsum += (v.x + v.y) + (v.z + v.w);
            }
        }

        // ---- block reduction ----
        #pragma unroll
        for (int off = 16; off > 0; off >>= 1)
            lsum += __shfl_down_sync(0xFFFFFFFFu, lsum, off);
        const int lane = tid & 31;
        const int wid  = tid >> 5;
        if (lane == 0) warpsums[wid] = lsum;
        __syncthreads();                 // also: all gather reads of srow are done
        if (wid == 0) {
            float s = (lane < (THREADS / 32)) ? warpsums[lane] : 0.0f;
            #pragma unroll
            for (int off = 8; off > 0; off >>= 1)
                s += __shfl_down_sync(0xFFFFFFFFu, s, off);
            if (lane == 0) s_mean = s;
        }
        __syncthreads();

        const float sub = (0.1f / (float)N) * s_mean;

        // ---- epilogue: subtract + relu, streaming float4 stores ----
        float4* out4 = (float4*)(out + (size_t)r * (size_t)N);
        #pragma unroll
        for (int k = 0; k < MAXCHUNK; ++k) {
            int i4 = tid + k * THREADS;
            if (i4 < n4) {
                float4 v = vals[k];
                float4 o;
                o.x = fmaxf(v.x - sub, 0.0f);
                o.y = fmaxf(v.y - sub, 0.0f);
                o.z = fmaxf(v.z - sub, 0.0f);
                o.w = fmaxf(v.w - sub, 0.0f);
                __stcs(out4 + i4, o);
            }
        }

        cur ^= 1;
    }
}

extern "C" void kernel_launch(void* const* d_in, const int* in_sizes, int n_in,
                              void* d_out, int out_size)
{
    const float* enc  = (const float*)d_in[0];
    const float* w    = (const float*)d_in[1];
    const int*   pref = (const int*)d_in[2];
    float*       out  = (float*)d_out;

    const int N = in_sizes[1];
    const int B = out_size / N;
    const int F = (int)((long long)in_sizes[0] / (long long)B);
    const int fmask = ((F & (F - 1)) == 0) ? (F - 1) : 0;

    int dev = 0;
    cudaGetDevice(&dev);
    int sms = 148;
    cudaDeviceGetAttribute(&sms, cudaDevAttrMultiProcessorCount, dev);
    int grid = (B < sms) ? B : sms;

    const int smem = 2 * F * (int)sizeof(float);
    cudaFuncSetAttribute(sensory_persistent,
                         cudaFuncAttributeMaxDynamicSharedMemorySize, smem);

    sensory_persistent<<<grid, THREADS, smem>>>(enc, w, pref, out, B, N, F, fmask);
}

// round 3
// speedup vs baseline: 1.2900x; 1.0434x over previous
#include <cuda_runtime.h>
#include <cstdint>

// Persistent kernel, 3-deep TMA ring buffer (prefetch depth 2).
// Each CTA owns rows blockIdx.x + k*gridDim.x. pref/weights pre-masked and
// register-resident. One __syncthreads per row (doubles as buffer release);
// final mean reduce is redundant-per-thread from smem broadcasts.

#define THREADS 512
#define MAXCHUNK 8   // N/4/THREADS = 16384/4/512
#define STAGES 3

__global__ __launch_bounds__(THREADS, 1)
void sensory_persistent3(const float* __restrict__ enc,
                         const float* __restrict__ w,
                         const int*   __restrict__ pref,
                         float* __restrict__ out,
                         int B, int N, int F, int fmask)
{
    extern __shared__ __align__(128) unsigned char smem_dyn[];
    __shared__ __align__(8) unsigned long long mbar[STAGES];
    __shared__ float warpsums[THREADS / 32];

    const int tid = threadIdx.x;
    const unsigned rowbytes = (unsigned)F * 4u;

    uint32_t b_bar[STAGES], b_buf[STAGES];
    #pragma unroll
    for (int s = 0; s < STAGES; ++s) {
        b_bar[s] = (uint32_t)__cvta_generic_to_shared(&mbar[s]);
        b_buf[s] = (uint32_t)__cvta_generic_to_shared(smem_dyn + (size_t)s * rowbytes);
    }

    if (tid == 0) {
        #pragma unroll
        for (int s = 0; s < STAGES; ++s)
            asm volatile("mbarrier.init.shared::cta.b64 [%0], 1;" :: "r"(b_bar[s]) : "memory");
        asm volatile("fence.proxy.async.shared::cta;" ::: "memory");
    }
    __syncthreads();

    // ---- preload prefs (byte offsets) and weights into registers ----
    const int n4 = N >> 2;
    int4   poff[MAXCHUNK];
    float4 wv[MAXCHUNK];
    {
        const int4*   pref4 = (const int4*)pref;
        const float4* w4    = (const float4*)w;
        #pragma unroll
        for (int k = 0; k < MAXCHUNK; ++k) {
            int i4 = tid + k * THREADS;
            if (i4 < n4) {
                int4 p = pref4[i4];
                if (fmask) {
                    p.x = (p.x & fmask) << 2;
                    p.y = (p.y & fmask) << 2;
                    p.z = (p.z & fmask) << 2;
                    p.w = (p.w & fmask) << 2;
                } else {
                    p.x = (int)((unsigned)p.x % (unsigned)F) << 2;
                    p.y = (int)((unsigned)p.y % (unsigned)F) << 2;
                    p.z = (int)((unsigned)p.z % (unsigned)F) << 2;
                    p.w = (int)((unsigned)p.w % (unsigned)F) << 2;
                }
                poff[k] = p;
                wv[k]   = w4[i4];
            }
        }
    }

    const int G = gridDim.x;

    // ---- prologue: issue first two rows ----
    if (tid == 0) {
        #pragma unroll
        for (int s = 0; s < 2; ++s) {
            int r = blockIdx.x + s * G;
            if (r < B) {
                asm volatile("mbarrier.arrive.expect_tx.shared::cta.b64 _, [%0], %1;"
                             :: "r"(b_bar[s]), "r"(rowbytes) : "memory");
                asm volatile("cp.async.bulk.shared::cta.global.mbarrier::complete_tx::bytes "
                             "[%0], [%1], %2, [%3];"
                             :: "r"(b_buf[s]), "l"(enc + (size_t)r * (size_t)F),
                                "r"(rowbytes), "r"(b_bar[s]) : "memory");
            }
        }
    }

    int cur = 0, nxt2 = 2;   // nxt2 = (cur + 2) % STAGES
    int par = 0;

    for (int r = blockIdx.x; r < B; r += G) {
        // ---- wait for current buffer ----
        {
            const uint32_t mb = b_bar[cur];
            uint32_t done;
            asm volatile("{ .reg .pred p; "
                         "mbarrier.try_wait.parity.acquire.cta.shared::cta.b64 p, [%1], %2; "
                         "selp.b32 %0, 1, 0, p; }"
                         : "=r"(done) : "r"(mb), "r"((uint32_t)par) : "memory");
            if (!done) {
                asm volatile("{ .reg .pred P1; "
                             "WL%=: mbarrier.try_wait.parity.acquire.cta.shared::cta.b64 P1, [%0], %1, 0x989680; "
                             "@P1 bra.uni WD%=; bra.uni WL%=; WD%=: }"
                             :: "r"(mb), "r"((uint32_t)par) : "memory");
            }
        }

        const char* srow = (const char*)smem_dyn + (size_t)cur * rowbytes;

        // ---- gather into registers + local sum ----
        float lsum = 0.0f;
        float4 vals[MAXCHUNK];
        #pragma unroll
        for (int k = 0; k < MAXCHUNK; ++k) {
            int i4 = tid + k * THREADS;
            if (i4 < n4) {
                float4 v;
                v.x = *(const float*)(srow + poff[k].x) * wv[k].x;
                v.y = *(const float*)(srow + poff[k].y) * wv[k].y;
                v.z = *(const float*)(srow + poff[k].z) * wv[k].z;
                v.w = *(const float*)(srow + poff[k].w) * wv[k].w;
                vals[k] = v;
                lsum += (v.x + v.y) + (v.z + v.w);
            }
        }

        // ---- warp partial sums ----
        #pragma unroll
        for (int off = 16; off > 0; off >>= 1)
            lsum += __shfl_down_sync(0xFFFFFFFFu, lsum, off);
        if ((tid & 31) == 0) warpsums[tid >> 5] = lsum;
        __syncthreads();   // sums visible AND all reads of srow complete -> buffer free

        // ---- issue TMA for row r + 2G into the buffer freed above ----
        {
            const int r2 = r + 2 * G;
            if (r2 < B && tid == 0) {
                asm volatile("mbarrier.arrive.expect_tx.shared::cta.b64 _, [%0], %1;"
                             :: "r"(b_bar[nxt2]), "r"(rowbytes) : "memory");
                asm volatile("cp.async.bulk.shared::cta.global.mbarrier::complete_tx::bytes "
                             "[%0], [%1], %2, [%3];"
                             :: "r"(b_buf[nxt2]), "l"(enc + (size_t)r2 * (size_t)F),
                                "r"(rowbytes), "r"(b_bar[nxt2]) : "memory");
            }
        }

        // ---- redundant per-thread final reduce (no second barrier) ----
        float tot = 0.0f;
        #pragma unroll
        for (int ws = 0; ws < THREADS / 32; ++ws) tot += warpsums[ws];
        const float sub = (0.1f / (float)N) * tot;

        // ---- epilogue: subtract + relu, streaming float4 stores ----
        float4* out4 = (float4*)(out + (size_t)r * (size_t)N);
        #pragma unroll
        for (int k = 0; k < MAXCHUNK; ++k) {
            int i4 = tid + k * THREADS;
            if (i4 < n4) {
                float4 v = vals[k];
                float4 o;
                o.x = fmaxf(v.x - sub, 0.0f);
                o.y = fmaxf(v.y - sub, 0.0f);
                o.z = fmaxf(v.z - sub, 0.0f);
                o.w = fmaxf(v.w - sub, 0.0f);
                __stcs(out4 + i4, o);
            }
        }

        // advance ring
        cur  = (cur == STAGES - 1) ? 0 : cur + 1;
        nxt2 = (nxt2 == STAGES - 1) ? 0 : nxt2 + 1;
        if (cur == 0) par ^= 1;
    }
}

extern "C" void kernel_launch(void* const* d_in, const int* in_sizes, int n_in,
                              void* d_out, int out_size)
{
    const float* enc  = (const float*)d_in[0];
    const float* w    = (const float*)d_in[1];
    const int*   pref = (const int*)d_in[2];
    float*       out  = (float*)d_out;

    const int N = in_sizes[1];
    const int B = out_size / N;
    const int F = (int)((long long)in_sizes[0] / (long long)B);
    const int fmask = ((F & (F - 1)) == 0) ? (F - 1) : 0;

    int dev = 0;
    cudaGetDevice(&dev);
    int sms = 148;
    cudaDeviceGetAttribute(&sms, cudaDevAttrMultiProcessorCount, dev);
    int grid = (B < sms) ? B : sms;

    const int smem = STAGES * F * (int)sizeof(float);
    cudaFuncSetAttribute(sensory_persistent3,
                         cudaFuncAttributeMaxDynamicSharedMemorySize, smem);

    sensory_persistent3<<<grid, THREADS, smem>>>(enc, w, pref, out, B, N, F, fmask);
}